// round 5
// baseline (speedup 1.0000x reference)
#include <cuda_runtime.h>
#include <cuda_fp16.h>

#define NN 50000
#define NE 600000
#define H  128
#define HV4 32          // H/4
#define GG 16
#define OUTD 14
#define NL 3
#define GEN_EPS 1e-7f
#define BN_EPS  1e-5f
#define BN_BLOCKS 256
#define BN_CHUNK  196     // ceil(50000/256)
#define NBC 391           // ceil(NN/128)  (embed / scan / gemm blocks)
#define MAXPART 800

// ---------------- scratch (device globals; no allocation allowed) ------------
__device__ float g_hv [NN * H];
__device__ float g_x  [NN * H];
__device__ uint2 g_h1 [NN * HV4];             // hv1 in fp16 (4 halves per uint2)
__device__ int   g_cnt[NN];
__device__ int   g_off[NN];
__device__ int   g_bsum[512];
__device__ int   g_boff[512];
__device__ int   g_edge[NE];                  // packed: src | (f0*3+f1)<<16
__device__ float g_part[2][MAXPART][H];
__device__ float g_scale[H];
__device__ float g_shift[H];
__device__ float g_etab[18 * H];
__device__ float g_hg[GG * H];
__device__ int   g_cntg[GG];

// node embedding + BN partial stats; also zeroes g_cnt for the CSR build.
__global__ void k_embed(const int* __restrict__ f0, const int* __restrict__ f1,
                        const float* __restrict__ W0, const float* __restrict__ W1) {
    __shared__ int sf0[128], sf1[128];
    int b = blockIdx.x, c = threadIdx.x;
    int n0 = b * 128;
    int cnt = min(128, NN - n0);
    if (c < cnt) {
        sf0[c] = f0[n0 + c]; sf1[c] = f1[n0 + c];
        g_cnt[n0 + c] = 0;
    }
    __syncthreads();
    float s = 0.f, ss = 0.f;
    for (int i = 0; i < cnt; i++) {
        float v = W0[sf0[i] * H + c] + W1[sf1[i] * H + c];
        g_hv[(n0 + i) * H + c] = v;
        s += v; ss += v * v;
    }
    g_part[0][b][c] = s;
    g_part[1][b][c] = ss;
}

// ---------------- CSR build (dst-sorted), hierarchical scan ------------------
__global__ void k_count(const int* __restrict__ dst) {
    int e = blockIdx.x * blockDim.x + threadIdx.x;
    if (e < NE) atomicAdd(&g_cnt[dst[e]], 1);
}

__global__ void k_scan1() {
    __shared__ int wsum[4];
    int b = blockIdx.x, t = threadIdx.x;
    int idx = b * 128 + t;
    int v = (idx < NN) ? g_cnt[idx] : 0;
    int s = v;
    for (int d = 16; d > 0; d >>= 1) s += __shfl_down_sync(0xffffffffu, s, d);
    if ((t & 31) == 0) wsum[t >> 5] = s;
    __syncthreads();
    if (t == 0) g_bsum[b] = wsum[0] + wsum[1] + wsum[2] + wsum[3];
}

__global__ void k_scan2() {   // also zeroes pool accumulators
    __shared__ int sm[512];
    int t = threadIdx.x;
    int v = (t < NBC) ? g_bsum[t] : 0;
    sm[t] = v;
    __syncthreads();
    for (int d = 1; d < 512; d <<= 1) {
        int u = (t >= d) ? sm[t - d] : 0;
        __syncthreads();
        sm[t] += u;
        __syncthreads();
    }
    if (t < NBC) g_boff[t] = sm[t] - v;
    for (int i = t; i < GG * H; i += 512) g_hg[i] = 0.f;
    if (t < GG) g_cntg[t] = 0;
}

__global__ void k_scan3() {
    __shared__ int wsum[4];
    int b = blockIdx.x, t = threadIdx.x;
    int idx = b * 128 + t;
    int v = (idx < NN) ? g_cnt[idx] : 0;
    int inc = v;
    for (int d = 1; d < 32; d <<= 1) {
        int u = __shfl_up_sync(0xffffffffu, inc, d);
        if ((t & 31) >= d) inc += u;
    }
    if ((t & 31) == 31) wsum[t >> 5] = inc;
    __syncthreads();
    int w = t >> 5;
    int woff = 0;
    for (int i = 0; i < 4; i++) if (i < w) woff += wsum[i];
    if (idx < NN) g_off[idx] = g_boff[b] + woff + inc - v;
}

// scatter edges; g_off used as cursor (post: g_off[v] = segment END)
__global__ void k_scatter(const int* __restrict__ src, const int* __restrict__ dst,
                          const int* __restrict__ f0, const int* __restrict__ f1) {
    int e = blockIdx.x * blockDim.x + threadIdx.x;
    if (e >= NE) return;
    int d = dst[e];
    int j = atomicAdd(&g_off[d], 1);
    g_edge[j] = src[e] | ((f0[e] * 3 + f1[e]) << 16);
}

// ---------------- BN finalize + combined edge table --------------------------
__global__ void k_bnfin(const float* __restrict__ gamma, const float* __restrict__ bnb,
                        const float* __restrict__ ee0, const float* __restrict__ ee1,
                        int l) {
    __shared__ float red[2][8][H];
    int tid = threadIdx.x;
    int c = tid & 127, g = tid >> 7;
    float s = 0.f, ss = 0.f;
    for (int b = g; b < NBC; b += 8) { s += g_part[0][b][c]; ss += g_part[1][b][c]; }
    red[0][g][c] = s; red[1][g][c] = ss;
    __syncthreads();
    if (tid < H) {
        float S = 0.f, SS = 0.f;
        for (int i = 0; i < 8; i++) { S += red[0][i][tid]; SS += red[1][i][tid]; }
        float mu  = S / (float)NN;
        float var = SS / (float)NN - mu * mu;
        float sc  = rsqrtf(var + BN_EPS) * gamma[l * H + tid];
        g_scale[tid] = sc;
        g_shift[tid] = bnb[l * H + tid] - mu * sc;
    }
    for (int i = tid; i < 18 * H; i += 1024) {
        int idx = i >> 7, cc = i & 127;
        int f0 = idx / 3, f1 = idx - f0 * 3;
        g_etab[i] = ee0[(l * 6 + f0) * H + cc] + ee1[(l * 3 + f1) * H + cc];
    }
}

// ---------------- BN apply -> fp16 hv1 buffer --------------------------------
__global__ void k_bnh() {
    int i = blockIdx.x * blockDim.x + threadIdx.x;   // over NN*HV4
    if (i >= NN * HV4) return;
    int q = i & 31;
    float4 v  = ((const float4*)g_hv)[i];
    float4 sc = ((const float4*)g_scale)[q];
    float4 sh = ((const float4*)g_shift)[q];
    float4 r;
    r.x = fmaxf(fmaf(v.x, sc.x, sh.x), 0.f);
    r.y = fmaxf(fmaf(v.y, sc.y, sh.y), 0.f);
    r.z = fmaxf(fmaf(v.z, sc.z, sh.z), 0.f);
    r.w = fmaxf(fmaf(v.w, sc.w, sh.w), 0.f);
    __half2 p0 = __floats2half2_rn(r.x, r.y);
    __half2 p1 = __floats2half2_rn(r.z, r.w);
    uint2 o;
    o.x = *(unsigned int*)&p0;
    o.y = *(unsigned int*)&p1;
    g_h1[i] = o;
}

// ---------------- GENConv aggregation: warp per dst node ---------------------
// hv1 gathered as fp16 (256B/edge = 2 cache lines).  agg = sum(m*e)/sum(e),
// e = exp(m*beta) (no max-shift: m in (0,~10]).  x = hv1 + agg.
__global__ void __launch_bounds__(256) k_agg(const float* __restrict__ beta, int l) {
    __shared__ float etab[18 * H];
    int tid = threadIdx.x;
    for (int i = tid; i < 18 * H; i += 256) etab[i] = g_etab[i];
    __syncthreads();
    int gt   = blockIdx.x * 256 + tid;
    int wid  = gt >> 5;
    int lane = tid & 31;
    if (wid >= NN) return;
    float bl = beta[l];
    int end = g_off[wid];
    int beg = end - g_cnt[wid];
    const uint2*  __restrict__ h1  = g_h1;
    const float4* __restrict__ et4 = (const float4*)etab;
    float4 num = make_float4(0.f, 0.f, 0.f, 0.f);
    float4 den = make_float4(0.f, 0.f, 0.f, 0.f);
#define EDGE_ELEM(hc, ec, nc, dc) do {                                    \
        float m_ = fmaxf((hc) + (ec), 0.f) + GEN_EPS;                     \
        float x_ = __expf(m_ * bl);                                       \
        dc += x_; nc = fmaf(m_, x_, nc); } while (0)
#define EDGE_ONE(pe) do {                                                 \
        int src_ = (pe) & 0xFFFF;                                         \
        int idx_ = (pe) >> 16;                                            \
        uint2 hp_ = h1[src_ * HV4 + lane];                                \
        float2 f0_ = __half22float2(*(__half2*)&hp_.x);                   \
        float2 f1_ = __half22float2(*(__half2*)&hp_.y);                   \
        float4 e_ = et4[idx_ * HV4 + lane];                               \
        EDGE_ELEM(f0_.x, e_.x, num.x, den.x);                             \
        EDGE_ELEM(f0_.y, e_.y, num.y, den.y);                             \
        EDGE_ELEM(f1_.x, e_.z, num.z, den.z);                             \
        EDGE_ELEM(f1_.y, e_.w, num.w, den.w); } while (0)
    int j = beg;
    for (; j + 2 <= end; j += 2) {
        int pe0 = g_edge[j], pe1 = g_edge[j + 1];
        EDGE_ONE(pe0);
        EDGE_ONE(pe1);
    }
    if (j < end) { int pe0 = g_edge[j]; EDGE_ONE(pe0); }
    uint2 hd = h1[wid * HV4 + lane];
    float2 d0 = __half22float2(*(__half2*)&hd.x);
    float2 d1 = __half22float2(*(__half2*)&hd.y);
    float4 xo = make_float4(d0.x, d0.y, d1.x, d1.y);
    if (end > beg) {
        xo.x += num.x / den.x;
        xo.y += num.y / den.y;
        xo.z += num.z / den.z;
        xo.w += num.w / den.w;
    }
    ((float4*)g_x)[wid * HV4 + lane] = xo;
}

// ---------------- MLP GEMM: hv = x @ W + b + hv, + BN partial stats ----------
// 128-row x 128-col tile, 256 threads, 8x8 register blocking.
// X staged TRANSPOSED in smem so the a-operand is 2x LDS.128 broadcast.
__global__ void __launch_bounds__(256) k_gemm(const float* __restrict__ W,
                                              const float* __restrict__ bias) {
    __shared__ float Ws[32 * H];        // 16 KB; reused for stat reduction
    __shared__ float XsT[32 * 132];     // 16.5 KB transposed (k-major), pad 132
    int tid = threadIdx.x;
    int tx = tid & 15, ty = tid >> 4;
    int row0 = blockIdx.x * 128;
    float acc[8][8];
#pragma unroll
    for (int i = 0; i < 8; i++)
#pragma unroll
        for (int j = 0; j < 8; j++) acc[i][j] = 0.f;

    for (int kk = 0; kk < H; kk += 32) {
        const float4* Wg  = (const float4*)(W + kk * H);
        float4*       Ws4 = (float4*)Ws;
#pragma unroll
        for (int i = 0; i < 4; i++) Ws4[tid + i * 256] = Wg[tid + i * 256];
#pragma unroll
        for (int i = 0; i < 4; i++) {
            int f  = tid + i * 256;              // 0..1023
            int r  = f >> 3, c4 = f & 7;
            int row = row0 + r;
            float4 v = make_float4(0.f, 0.f, 0.f, 0.f);
            if (row < NN) v = ((const float4*)(g_x + row * H + kk))[c4];
            XsT[(c4 * 4 + 0) * 132 + r] = v.x;
            XsT[(c4 * 4 + 1) * 132 + r] = v.y;
            XsT[(c4 * 4 + 2) * 132 + r] = v.z;
            XsT[(c4 * 4 + 3) * 132 + r] = v.w;
        }
        __syncthreads();
#pragma unroll
        for (int k = 0; k < 32; k++) {
            float4 a0 = *(const float4*)&XsT[k * 132 + ty * 8];
            float4 a1 = *(const float4*)&XsT[k * 132 + ty * 8 + 4];
            float4 b0 = *(const float4*)&Ws[k * H + tx * 8];
            float4 b1 = *(const float4*)&Ws[k * H + tx * 8 + 4];
            float a[8] = {a0.x, a0.y, a0.z, a0.w, a1.x, a1.y, a1.z, a1.w};
            float b[8] = {b0.x, b0.y, b0.z, b0.w, b1.x, b1.y, b1.z, b1.w};
#pragma unroll
            for (int i = 0; i < 8; i++)
#pragma unroll
                for (int j = 0; j < 8; j++) acc[i][j] += a[i] * b[j];
        }
        __syncthreads();
    }
    // epilogue: out = acc + bias + hv_old; accumulate BN partial stats
    float4 br0 = ((const float4*)(bias + tx * 8))[0];
    float4 br1 = ((const float4*)(bias + tx * 8))[1];
    float br[8] = {br0.x, br0.y, br0.z, br0.w, br1.x, br1.y, br1.z, br1.w};
    float s_loc[8], ss_loc[8];
#pragma unroll
    for (int j = 0; j < 8; j++) { s_loc[j] = 0.f; ss_loc[j] = 0.f; }
#pragma unroll
    for (int i = 0; i < 8; i++) {
        int row = row0 + ty * 8 + i;
        if (row < NN) {
            float4* hr = (float4*)(g_hv + row * H + tx * 8);
            float4 h0 = hr[0], h1 = hr[1];
            float hold[8] = {h0.x, h0.y, h0.z, h0.w, h1.x, h1.y, h1.z, h1.w};
            float v[8];
#pragma unroll
            for (int j = 0; j < 8; j++) v[j] = acc[i][j] + br[j] + hold[j];
            hr[0] = make_float4(v[0], v[1], v[2], v[3]);
            hr[1] = make_float4(v[4], v[5], v[6], v[7]);
#pragma unroll
            for (int j = 0; j < 8; j++) { s_loc[j] += v[j]; ss_loc[j] += v[j] * v[j]; }
        }
    }
    __syncthreads();
#pragma unroll
    for (int j = 0; j < 8; j++) {
        int ch = tx * 8 + j;
        Ws[ty * H + ch]        = s_loc[j];
        Ws[2048 + ty * H + ch] = ss_loc[j];
    }
    __syncthreads();
    if (tid < H) {
        float s = 0.f, ss = 0.f;
#pragma unroll
        for (int g = 0; g < 16; g++) { s += Ws[g * H + tid]; ss += Ws[2048 + g * H + tid]; }
        g_part[0][blockIdx.x][tid] = s;
        g_part[1][blockIdx.x][tid] = ss;
    }
}

// ---------------- graph pooling + output head --------------------------------
__global__ void k_pool(const int* __restrict__ gid) {
    int b = blockIdx.x, c = threadIdx.x;
    int n0 = b * BN_CHUNK;
    int n1 = min(NN, n0 + BN_CHUNK);
    if (n0 >= NN) return;
    float acc = 0.f;
    int curg = gid[n0];
    int run = 0;
    for (int n = n0; n < n1; n++) {
        int g = gid[n];
        if (g != curg) {
            atomicAdd(&g_hg[curg * H + c], acc);
            if (c == 0) atomicAdd(&g_cntg[curg], run);
            acc = 0.f; run = 0; curg = g;
        }
        acc += g_hv[n * H + c];
        run++;
    }
    atomicAdd(&g_hg[curg * H + c], acc);
    if (c == 0) atomicAdd(&g_cntg[curg], run);
}

__global__ void k_out(const float* __restrict__ Wo, const float* __restrict__ bo,
                      float* __restrict__ out) {
    int t = threadIdx.x;
    if (t >= GG * OUTD) return;
    int g = t / OUTD, o = t % OUTD;
    float inv = 1.f / (float)g_cntg[g];
    float acc = bo[o];
    for (int h = 0; h < H; h++) acc += g_hg[g * H + h] * inv * Wo[h * OUTD + o];
    out[t] = acc;
}

// ---------------- launch -----------------------------------------------------
extern "C" void kernel_launch(void* const* d_in, const int* in_sizes, int n_in,
                              void* d_out, int out_size) {
    const int* nf0  = (const int*)d_in[0];
    const int* nf1  = (const int*)d_in[1];
    const int* ef0  = (const int*)d_in[2];
    const int* ef1  = (const int*)d_in[3];
    const int* esrc = (const int*)d_in[4];
    const int* edst = (const int*)d_in[5];
    const int* gid  = (const int*)d_in[6];
    int base = (n_in > 7 && in_sizes[7] == 1) ? 8 : 7;
    const float* Wn0  = (const float*)d_in[base + 0];
    const float* Wn1  = (const float*)d_in[base + 1];
    const float* ee0  = (const float*)d_in[base + 2];
    const float* ee1  = (const float*)d_in[base + 3];
    const float* beta = (const float*)d_in[base + 4];
    const float* mlpW = (const float*)d_in[base + 5];
    const float* mlpb = (const float*)d_in[base + 6];
    const float* gam  = (const float*)d_in[base + 7];
    const float* bnb  = (const float*)d_in[base + 8];
    const float* Wo   = (const float*)d_in[base + 9];
    const float* bo   = (const float*)d_in[base + 10];
    float* out = (float*)d_out;

    k_embed<<<NBC, 128>>>(nf0, nf1, Wn0, Wn1);
    k_count<<<(NE + 255) / 256, 256>>>(edst);
    k_scan1<<<NBC, 128>>>();
    k_scan2<<<1, 512>>>();
    k_scan3<<<NBC, 128>>>();
    k_scatter<<<(NE + 255) / 256, 256>>>(esrc, edst, ef0, ef1);

    for (int l = 0; l < NL; l++) {
        k_bnfin<<<1, 1024>>>(gam, bnb, ee0, ee1, l);
        k_bnh<<<(NN * HV4 + 255) / 256, 256>>>();
        k_agg<<<(NN * 32 + 255) / 256, 256>>>(beta, l);
        k_gemm<<<NBC, 256>>>(mlpW + (size_t)l * H * H, mlpb + (size_t)l * H);
    }

    k_pool<<<BN_BLOCKS, H>>>(gid);
    k_out<<<1, 256>>>(Wo, bo, out);
}

// round 7
// speedup vs baseline: 1.0754x; 1.0754x over previous
#include <cuda_runtime.h>
#include <cuda_fp16.h>
#include <cstdint>

#define NN 50000
#define NE 600000
#define H  128
#define HV4 32          // H/4
#define GG 16
#define OUTD 14
#define NL 3
#define GEN_EPS 1e-7f
#define BN_EPS  1e-5f
#define BN_BLOCKS 256
#define BN_CHUNK  196     // ceil(50000/256)
#define NBC 391           // ceil(NN/128)
#define MAXPART 800

// ---------------- scratch (device globals; no allocation allowed) ------------
__device__ float  g_hv [NN * H];
__device__ __align__(16) uint2  g_xh [NN * HV4];   // x fp16 (GEMM A), 4 halves/uint2
__device__ __align__(16) uint2  g_h1 [NN * HV4];   // hv1 fp16
__device__ __align__(16) __half g_wh [H * H];      // W^T fp16 [n][k], current layer
__device__ int    g_cnt[NN];
__device__ int    g_off[NN];
__device__ int    g_bsum[512];
__device__ int    g_boff[512];
__device__ int    g_edge[NE];                 // packed: src | (f0*3+f1)<<16
__device__ float  g_part[2][MAXPART][H];
__device__ float  g_scale[H];
__device__ float  g_shift[H];
__device__ float  g_etab[18 * H];
__device__ float  g_hg[GG * H];
__device__ int    g_cntg[GG];

__device__ __forceinline__ uint32_t su32(const void* p) {
    uint32_t a;
    asm("{ .reg .u64 t; cvta.to.shared.u64 t, %1; cvt.u32.u64 %0, t; }" : "=r"(a) : "l"(p));
    return a;
}

// node embedding + BN partial stats; also zeroes g_cnt for the CSR build.
__global__ void k_embed(const int* __restrict__ f0, const int* __restrict__ f1,
                        const float* __restrict__ W0, const float* __restrict__ W1) {
    __shared__ int sf0[128], sf1[128];
    int b = blockIdx.x, c = threadIdx.x;
    int n0 = b * 128;
    int cnt = min(128, NN - n0);
    if (c < cnt) {
        sf0[c] = f0[n0 + c]; sf1[c] = f1[n0 + c];
        g_cnt[n0 + c] = 0;
    }
    __syncthreads();
    float s = 0.f, ss = 0.f;
    for (int i = 0; i < cnt; i++) {
        float v = W0[sf0[i] * H + c] + W1[sf1[i] * H + c];
        g_hv[(n0 + i) * H + c] = v;
        s += v; ss += v * v;
    }
    g_part[0][b][c] = s;
    g_part[1][b][c] = ss;
}

// BN partial stats over current g_hv (after a GEMM layer)
__global__ void k_stats() {
    int b = blockIdx.x, c = threadIdx.x;
    int n0 = b * 128;
    int cnt = min(128, NN - n0);
    float s = 0.f, ss = 0.f;
    for (int i = 0; i < cnt; i++) {
        float v = g_hv[(n0 + i) * H + c];
        s += v; ss += v * v;
    }
    g_part[0][b][c] = s;
    g_part[1][b][c] = ss;
}

// ---------------- CSR build (dst-sorted), hierarchical scan ------------------
__global__ void k_count(const int* __restrict__ dst) {
    int e = blockIdx.x * blockDim.x + threadIdx.x;
    if (e < NE) atomicAdd(&g_cnt[dst[e]], 1);
}

__global__ void k_scan1() {
    __shared__ int wsum[4];
    int b = blockIdx.x, t = threadIdx.x;
    int idx = b * 128 + t;
    int v = (idx < NN) ? g_cnt[idx] : 0;
    int s = v;
    for (int d = 16; d > 0; d >>= 1) s += __shfl_down_sync(0xffffffffu, s, d);
    if ((t & 31) == 0) wsum[t >> 5] = s;
    __syncthreads();
    if (t == 0) g_bsum[b] = wsum[0] + wsum[1] + wsum[2] + wsum[3];
}

__global__ void k_scan2() {   // also zeroes pool accumulators
    __shared__ int sm[512];
    int t = threadIdx.x;
    int v = (t < NBC) ? g_bsum[t] : 0;
    sm[t] = v;
    __syncthreads();
    for (int d = 1; d < 512; d <<= 1) {
        int u = (t >= d) ? sm[t - d] : 0;
        __syncthreads();
        sm[t] += u;
        __syncthreads();
    }
    if (t < NBC) g_boff[t] = sm[t] - v;
    for (int i = t; i < GG * H; i += 512) g_hg[i] = 0.f;
    if (t < GG) g_cntg[t] = 0;
}

__global__ void k_scan3() {
    __shared__ int wsum[4];
    int b = blockIdx.x, t = threadIdx.x;
    int idx = b * 128 + t;
    int v = (idx < NN) ? g_cnt[idx] : 0;
    int inc = v;
    for (int d = 1; d < 32; d <<= 1) {
        int u = __shfl_up_sync(0xffffffffu, inc, d);
        if ((t & 31) >= d) inc += u;
    }
    if ((t & 31) == 31) wsum[t >> 5] = inc;
    __syncthreads();
    int w = t >> 5;
    int woff = 0;
    for (int i = 0; i < 4; i++) if (i < w) woff += wsum[i];
    if (idx < NN) g_off[idx] = g_boff[b] + woff + inc - v;
}

// scatter edges; g_off used as cursor (post: g_off[v] = segment END)
__global__ void k_scatter(const int* __restrict__ src, const int* __restrict__ dst,
                          const int* __restrict__ f0, const int* __restrict__ f1) {
    int e = blockIdx.x * blockDim.x + threadIdx.x;
    if (e >= NE) return;
    int d = dst[e];
    int j = atomicAdd(&g_off[d], 1);
    g_edge[j] = src[e] | ((f0[e] * 3 + f1[e]) << 16);
}

// ------- BN finalize + combined edge table + W transpose to fp16 -------------
__global__ void k_bnfin(const float* __restrict__ gamma, const float* __restrict__ bnb,
                        const float* __restrict__ ee0, const float* __restrict__ ee1,
                        const float* __restrict__ W, int l) {
    __shared__ float red[2][8][H];
    int tid = threadIdx.x;
    int c = tid & 127, g = tid >> 7;
    float s = 0.f, ss = 0.f;
    for (int b = g; b < NBC; b += 8) { s += g_part[0][b][c]; ss += g_part[1][b][c]; }
    red[0][g][c] = s; red[1][g][c] = ss;
    __syncthreads();
    if (tid < H) {
        float S = 0.f, SS = 0.f;
        for (int i = 0; i < 8; i++) { S += red[0][i][tid]; SS += red[1][i][tid]; }
        float mu  = S / (float)NN;
        float var = fmaxf(SS / (float)NN - mu * mu, 0.f);
        float sc  = rsqrtf(var + BN_EPS) * gamma[l * H + tid];
        g_scale[tid] = sc;
        g_shift[tid] = bnb[l * H + tid] - mu * sc;
    }
    for (int i = tid; i < 18 * H; i += 1024) {
        int idx = i >> 7, cc = i & 127;
        int f0 = idx / 3, f1 = idx - f0 * 3;
        g_etab[i] = ee0[(l * 6 + f0) * H + cc] + ee1[(l * 3 + f1) * H + cc];
    }
    // W^T -> fp16 (n-major) for the HMMA GEMM
    for (int i = tid; i < H * H; i += 1024) {
        int n = i >> 7, k = i & 127;
        g_wh[n * H + k] = __float2half(W[k * H + n]);
    }
}

// ---------------- BN apply -> fp16 hv1 buffer --------------------------------
__global__ void k_bnh() {
    int i = blockIdx.x * blockDim.x + threadIdx.x;   // over NN*HV4
    if (i >= NN * HV4) return;
    int q = i & 31;
    float4 v  = ((const float4*)g_hv)[i];
    float4 sc = ((const float4*)g_scale)[q];
    float4 sh = ((const float4*)g_shift)[q];
    float4 r;
    r.x = fmaxf(fmaf(v.x, sc.x, sh.x), 0.f);
    r.y = fmaxf(fmaf(v.y, sc.y, sh.y), 0.f);
    r.z = fmaxf(fmaf(v.z, sc.z, sh.z), 0.f);
    r.w = fmaxf(fmaf(v.w, sc.w, sh.w), 0.f);
    __half2 p0 = __floats2half2_rn(r.x, r.y);
    __half2 p1 = __floats2half2_rn(r.z, r.w);
    uint2 o;
    o.x = *(unsigned int*)&p0;
    o.y = *(unsigned int*)&p1;
    g_h1[i] = o;
}

// ---------------- GENConv aggregation: warp per dst node ---------------------
// x = hv1 + sum(m*e)/sum(e), written as fp16 (GEMM A operand).
__global__ void __launch_bounds__(256) k_agg(const float* __restrict__ beta, int l) {
    __shared__ float etab[18 * H];
    int tid = threadIdx.x;
    for (int i = tid; i < 18 * H; i += 256) etab[i] = g_etab[i];
    __syncthreads();
    int gt   = blockIdx.x * 256 + tid;
    int wid  = gt >> 5;
    int lane = tid & 31;
    if (wid >= NN) return;
    float bl = beta[l];
    int end = g_off[wid];
    int beg = end - g_cnt[wid];
    const uint2*  __restrict__ h1  = g_h1;
    const float4* __restrict__ et4 = (const float4*)etab;
    float4 num = make_float4(0.f, 0.f, 0.f, 0.f);
    float4 den = make_float4(0.f, 0.f, 0.f, 0.f);
#define EDGE_ELEM(hc, ec, nc, dc) do {                                    \
        float m_ = fmaxf((hc) + (ec), 0.f) + GEN_EPS;                     \
        float x_ = __expf(m_ * bl);                                       \
        dc += x_; nc = fmaf(m_, x_, nc); } while (0)
#define EDGE_ONE(pe) do {                                                 \
        int src_ = (pe) & 0xFFFF;                                         \
        int idx_ = (pe) >> 16;                                            \
        uint2 hp_ = h1[src_ * HV4 + lane];                                \
        float2 f0_ = __half22float2(*(__half2*)&hp_.x);                   \
        float2 f1_ = __half22float2(*(__half2*)&hp_.y);                   \
        float4 e_ = et4[idx_ * HV4 + lane];                               \
        EDGE_ELEM(f0_.x, e_.x, num.x, den.x);                             \
        EDGE_ELEM(f0_.y, e_.y, num.y, den.y);                             \
        EDGE_ELEM(f1_.x, e_.z, num.z, den.z);                             \
        EDGE_ELEM(f1_.y, e_.w, num.w, den.w); } while (0)
    int j = beg;
    for (; j + 2 <= end; j += 2) {
        int pe0 = g_edge[j], pe1 = g_edge[j + 1];
        EDGE_ONE(pe0);
        EDGE_ONE(pe1);
    }
    if (j < end) { int pe0 = g_edge[j]; EDGE_ONE(pe0); }
    uint2 hd = h1[wid * HV4 + lane];
    float2 d0 = __half22float2(*(__half2*)&hd.x);
    float2 d1 = __half22float2(*(__half2*)&hd.y);
    float4 xo = make_float4(d0.x, d0.y, d1.x, d1.y);
    if (end > beg) {
        xo.x += num.x / den.x;
        xo.y += num.y / den.y;
        xo.z += num.z / den.z;
        xo.w += num.w / den.w;
    }
    __half2 p0 = __floats2half2_rn(xo.x, xo.y);
    __half2 p1 = __floats2half2_rn(xo.z, xo.w);
    uint2 o;
    o.x = *(unsigned int*)&p0;
    o.y = *(unsigned int*)&p1;
    g_xh[wid * HV4 + lane] = o;
}

// ---------------- MLP GEMM via HMMA: hv = x @ W + b + hv ---------------------
// 128x128 tile per block, 8 warps, mma.sync m16n8k16 f16->f32.
// K chunked in halves of 64 (smem = 2 x 128x72 halves = 36 KB, stride 144B).
__global__ void __launch_bounds__(256) k_gemm(const float* __restrict__ bias) {
    __shared__ __align__(16) __half As[128 * 72];
    __shared__ __align__(16) __half Bs[128 * 72];
    int tid = threadIdx.x;
    int warp = tid >> 5, lane = tid & 31;
    int row0 = blockIdx.x * 128;
    const __half* xh = (const __half*)g_xh;

    float acc[16][4];
#pragma unroll
    for (int t = 0; t < 16; t++)
#pragma unroll
        for (int j = 0; j < 4; j++) acc[t][j] = 0.f;

#pragma unroll
    for (int kk = 0; kk < H; kk += 64) {
        // stage A (zero-fill rows past NN) and B for this k-chunk
#pragma unroll
        for (int i = 0; i < 4; i++) {
            int f = tid + i * 256;           // 0..1023
            int r = f >> 3, c8 = f & 7;      // 8 uint4 per 64-half row
            uint4 v = make_uint4(0, 0, 0, 0);
            if (row0 + r < NN) v = ((const uint4*)(xh + (size_t)(row0 + r) * H + kk))[c8];
            *(uint4*)&As[r * 72 + c8 * 8] = v;
            uint4 w = ((const uint4*)(g_wh + r * H + kk))[c8];
            *(uint4*)&Bs[r * 72 + c8 * 8] = w;
        }
        __syncthreads();
        uint32_t a_row = su32(&As[(warp * 16 + (lane & 15)) * 72 + ((lane >> 4) * 8)]);
#pragma unroll
        for (int k = 0; k < 4; k++) {
            uint32_t a0, a1, a2, a3;
            asm volatile("ldmatrix.sync.aligned.m8n8.x4.shared.b16 {%0,%1,%2,%3}, [%4];"
                         : "=r"(a0), "=r"(a1), "=r"(a2), "=r"(a3)
                         : "r"(a_row + k * 32));
#pragma unroll
            for (int p = 0; p < 8; p++) {
                int brow = p * 16 + ((lane >> 4) << 3) + (lane & 7);
                int bcol = k * 16 + ((lane >> 3) & 1) * 8;
                uint32_t baddr = su32(&Bs[brow * 72 + bcol]);
                uint32_t b0, b1, b2, b3;
                asm volatile("ldmatrix.sync.aligned.m8n8.x4.shared.b16 {%0,%1,%2,%3}, [%4];"
                             : "=r"(b0), "=r"(b1), "=r"(b2), "=r"(b3)
                             : "r"(baddr));
                asm volatile("mma.sync.aligned.m16n8k16.row.col.f32.f16.f16.f32 "
                             "{%0,%1,%2,%3}, {%4,%5,%6,%7}, {%8,%9}, {%0,%1,%2,%3};"
                             : "+f"(acc[2 * p][0]), "+f"(acc[2 * p][1]),
                               "+f"(acc[2 * p][2]), "+f"(acc[2 * p][3])
                             : "r"(a0), "r"(a1), "r"(a2), "r"(a3), "r"(b0), "r"(b1));
                asm volatile("mma.sync.aligned.m16n8k16.row.col.f32.f16.f16.f32 "
                             "{%0,%1,%2,%3}, {%4,%5,%6,%7}, {%8,%9}, {%0,%1,%2,%3};"
                             : "+f"(acc[2 * p + 1][0]), "+f"(acc[2 * p + 1][1]),
                               "+f"(acc[2 * p + 1][2]), "+f"(acc[2 * p + 1][3])
                             : "r"(a0), "r"(a1), "r"(a2), "r"(a3), "r"(b2), "r"(b3));
            }
        }
        __syncthreads();
    }
    // epilogue: C[r][c] + bias[c] + hv_old -> g_hv
    int q = lane & 3, tq = lane >> 2;
    int r0 = row0 + warp * 16 + tq;
    int r1 = r0 + 8;
#pragma unroll
    for (int nt = 0; nt < 16; nt++) {
        int c = nt * 8 + 2 * q;
        float2 bb = *(const float2*)&bias[c];
        if (r0 < NN) {
            float2* h = (float2*)&g_hv[(size_t)r0 * H + c];
            float2 hv = *h;
            h->x = acc[nt][0] + bb.x + hv.x;
            h->y = acc[nt][1] + bb.y + hv.y;
        }
        if (r1 < NN) {
            float2* h = (float2*)&g_hv[(size_t)r1 * H + c];
            float2 hv = *h;
            h->x = acc[nt][2] + bb.x + hv.x;
            h->y = acc[nt][3] + bb.y + hv.y;
        }
    }
}

// ---------------- graph pooling + output head --------------------------------
__global__ void k_pool(const int* __restrict__ gid) {
    int b = blockIdx.x, c = threadIdx.x;
    int n0 = b * BN_CHUNK;
    int n1 = min(NN, n0 + BN_CHUNK);
    if (n0 >= NN) return;
    float acc = 0.f;
    int curg = gid[n0];
    int run = 0;
    for (int n = n0; n < n1; n++) {
        int g = gid[n];
        if (g != curg) {
            atomicAdd(&g_hg[curg * H + c], acc);
            if (c == 0) atomicAdd(&g_cntg[curg], run);
            acc = 0.f; run = 0; curg = g;
        }
        acc += g_hv[n * H + c];
        run++;
    }
    atomicAdd(&g_hg[curg * H + c], acc);
    if (c == 0) atomicAdd(&g_cntg[curg], run);
}

__global__ void k_out(const float* __restrict__ Wo, const float* __restrict__ bo,
                      float* __restrict__ out) {
    int t = threadIdx.x;
    if (t >= GG * OUTD) return;
    int g = t / OUTD, o = t % OUTD;
    float inv = 1.f / (float)g_cntg[g];
    float acc = bo[o];
    for (int h = 0; h < H; h++) acc += g_hg[g * H + h] * inv * Wo[h * OUTD + o];
    out[t] = acc;
}

// ---------------- launch -----------------------------------------------------
extern "C" void kernel_launch(void* const* d_in, const int* in_sizes, int n_in,
                              void* d_out, int out_size) {
    const int* nf0  = (const int*)d_in[0];
    const int* nf1  = (const int*)d_in[1];
    const int* ef0  = (const int*)d_in[2];
    const int* ef1  = (const int*)d_in[3];
    const int* esrc = (const int*)d_in[4];
    const int* edst = (const int*)d_in[5];
    const int* gid  = (const int*)d_in[6];
    int base = (n_in > 7 && in_sizes[7] == 1) ? 8 : 7;
    const float* Wn0  = (const float*)d_in[base + 0];
    const float* Wn1  = (const float*)d_in[base + 1];
    const float* ee0  = (const float*)d_in[base + 2];
    const float* ee1  = (const float*)d_in[base + 3];
    const float* beta = (const float*)d_in[base + 4];
    const float* mlpW = (const float*)d_in[base + 5];
    const float* mlpb = (const float*)d_in[base + 6];
    const float* gam  = (const float*)d_in[base + 7];
    const float* bnb  = (const float*)d_in[base + 8];
    const float* Wo   = (const float*)d_in[base + 9];
    const float* bo   = (const float*)d_in[base + 10];
    float* out = (float*)d_out;

    k_embed<<<NBC, 128>>>(nf0, nf1, Wn0, Wn1);
    k_count<<<(NE + 255) / 256, 256>>>(edst);
    k_scan1<<<NBC, 128>>>();
    k_scan2<<<1, 512>>>();
    k_scan3<<<NBC, 128>>>();
    k_scatter<<<(NE + 255) / 256, 256>>>(esrc, edst, ef0, ef1);

    for (int l = 0; l < NL; l++) {
        k_bnfin<<<1, 1024>>>(gam, bnb, ee0, ee1, mlpW + (size_t)l * H * H, l);
        k_bnh<<<(NN * HV4 + 255) / 256, 256>>>();
        k_agg<<<(NN * 32 + 255) / 256, 256>>>(beta, l);
        k_gemm<<<NBC, 256>>>(mlpb + (size_t)l * H);
        if (l < NL - 1) k_stats<<<NBC, 128>>>();
    }

    k_pool<<<BN_BLOCKS, H>>>(gid);
    k_out<<<1, 256>>>(Wo, bo, out);
}

// round 8
// speedup vs baseline: 1.1443x; 1.0641x over previous
#include <cuda_runtime.h>
#include <cuda_fp16.h>
#include <cstdint>

#define NN 50000
#define NE 600000
#define H  128
#define HV4 32          // H/4
#define GG 16
#define OUTD 14
#define NL 3
#define GEN_EPS 1e-7f
#define BN_EPS  1e-5f
#define BN_BLOCKS 256
#define BN_CHUNK  196     // ceil(50000/256)
#define NBC 391           // ceil(NN/128)
#define MAXPART 800

// ---------------- scratch (device globals; no allocation allowed) ------------
__device__ float  g_hv [NN * H];
__device__ __align__(16) uint2  g_xh [NN * HV4];   // x fp16 (GEMM A), 4 halves/uint2
__device__ __align__(16) __half g_wh [NL * H * H]; // W^T fp16 [l][n][k]
__device__ int    g_cnt[NN];
__device__ int    g_off[NN];
__device__ int    g_bsum[512];
__device__ int    g_boff[512];
__device__ int    g_edge[NE];                 // packed: src | (f0*3+f1)<<16
__device__ float  g_part[2][MAXPART][H];
__device__ float  g_scale[H];
__device__ float  g_shift[H];
__device__ float  g_etab[18 * H];
__device__ float  g_hg[GG * H];
__device__ int    g_cntg[GG];

__device__ __forceinline__ uint32_t su32(const void* p) {
    uint32_t a;
    asm("{ .reg .u64 t; cvta.to.shared.u64 t, %1; cvt.u32.u64 %0, t; }" : "=r"(a) : "l"(p));
    return a;
}

// ------- one-shot coalesced W^T -> fp16 for all layers -----------------------
__global__ void k_wt(const float* __restrict__ W) {
    __shared__ float t[32][33];
    int l = blockIdx.z;
    int bk = blockIdx.x, bn = blockIdx.y;
    int tx = threadIdx.x, ty = threadIdx.y;    // 32 x 8
    const float* Wl = W + (size_t)l * H * H;
#pragma unroll
    for (int i = 0; i < 4; i++)
        t[ty + i * 8][tx] = Wl[(bk * 32 + ty + i * 8) * H + bn * 32 + tx];
    __syncthreads();
    __half* out = g_wh + (size_t)l * H * H;
#pragma unroll
    for (int i = 0; i < 4; i++)
        out[(bn * 32 + ty + i * 8) * H + bk * 32 + tx] = __float2half(t[tx][ty + i * 8]);
}

// node embedding + BN partial stats; also zeroes g_cnt for the CSR build.
__global__ void k_embed(const int* __restrict__ f0, const int* __restrict__ f1,
                        const float* __restrict__ W0, const float* __restrict__ W1) {
    __shared__ int sf0[128], sf1[128];
    int b = blockIdx.x, c = threadIdx.x;
    int n0 = b * 128;
    int cnt = min(128, NN - n0);
    if (c < cnt) {
        sf0[c] = f0[n0 + c]; sf1[c] = f1[n0 + c];
        g_cnt[n0 + c] = 0;
    }
    __syncthreads();
    float s = 0.f, ss = 0.f;
    for (int i = 0; i < cnt; i++) {
        float v = W0[sf0[i] * H + c] + W1[sf1[i] * H + c];
        g_hv[(n0 + i) * H + c] = v;
        s += v; ss += v * v;
    }
    g_part[0][b][c] = s;
    g_part[1][b][c] = ss;
}

// ---------------- CSR build (dst-sorted), hierarchical scan ------------------
__global__ void k_count(const int* __restrict__ dst) {
    int e = blockIdx.x * blockDim.x + threadIdx.x;
    if (e < NE) atomicAdd(&g_cnt[dst[e]], 1);
}

__global__ void k_scan1() {
    __shared__ int wsum[4];
    int b = blockIdx.x, t = threadIdx.x;
    int idx = b * 128 + t;
    int v = (idx < NN) ? g_cnt[idx] : 0;
    int s = v;
    for (int d = 16; d > 0; d >>= 1) s += __shfl_down_sync(0xffffffffu, s, d);
    if ((t & 31) == 0) wsum[t >> 5] = s;
    __syncthreads();
    if (t == 0) g_bsum[b] = wsum[0] + wsum[1] + wsum[2] + wsum[3];
}

__global__ void k_scan2() {   // also zeroes pool accumulators
    __shared__ int sm[512];
    int t = threadIdx.x;
    int v = (t < NBC) ? g_bsum[t] : 0;
    sm[t] = v;
    __syncthreads();
    for (int d = 1; d < 512; d <<= 1) {
        int u = (t >= d) ? sm[t - d] : 0;
        __syncthreads();
        sm[t] += u;
        __syncthreads();
    }
    if (t < NBC) g_boff[t] = sm[t] - v;
    for (int i = t; i < GG * H; i += 512) g_hg[i] = 0.f;
    if (t < GG) g_cntg[t] = 0;
}

__global__ void k_scan3() {
    __shared__ int wsum[4];
    int b = blockIdx.x, t = threadIdx.x;
    int idx = b * 128 + t;
    int v = (idx < NN) ? g_cnt[idx] : 0;
    int inc = v;
    for (int d = 1; d < 32; d <<= 1) {
        int u = __shfl_up_sync(0xffffffffu, inc, d);
        if ((t & 31) >= d) inc += u;
    }
    if ((t & 31) == 31) wsum[t >> 5] = inc;
    __syncthreads();
    int w = t >> 5;
    int woff = 0;
    for (int i = 0; i < 4; i++) if (i < w) woff += wsum[i];
    if (idx < NN) g_off[idx] = g_boff[b] + woff + inc - v;
}

// scatter edges; g_off used as cursor (post: g_off[v] = segment END)
__global__ void k_scatter(const int* __restrict__ src, const int* __restrict__ dst,
                          const int* __restrict__ f0, const int* __restrict__ f1) {
    int e = blockIdx.x * blockDim.x + threadIdx.x;
    if (e >= NE) return;
    int d = dst[e];
    int j = atomicAdd(&g_off[d], 1);
    g_edge[j] = src[e] | ((f0[e] * 3 + f1[e]) << 16);
}

// ------------- BN finalize + combined edge table -----------------------------
__global__ void k_bnfin(const float* __restrict__ gamma, const float* __restrict__ bnb,
                        const float* __restrict__ ee0, const float* __restrict__ ee1,
                        int l) {
    __shared__ float red[2][8][H];
    int tid = threadIdx.x;
    int c = tid & 127, g = tid >> 7;
    float s = 0.f, ss = 0.f;
    for (int b = g; b < NBC; b += 8) { s += g_part[0][b][c]; ss += g_part[1][b][c]; }
    red[0][g][c] = s; red[1][g][c] = ss;
    __syncthreads();
    if (tid < H) {
        float S = 0.f, SS = 0.f;
        for (int i = 0; i < 8; i++) { S += red[0][i][tid]; SS += red[1][i][tid]; }
        float mu  = S / (float)NN;
        float var = fmaxf(SS / (float)NN - mu * mu, 0.f);
        float sc  = rsqrtf(var + BN_EPS) * gamma[l * H + tid];
        g_scale[tid] = sc;
        g_shift[tid] = bnb[l * H + tid] - mu * sc;
    }
    for (int i = tid; i < 18 * H; i += 1024) {
        int idx = i >> 7, cc = i & 127;
        int f0 = idx / 3, f1 = idx - f0 * 3;
        g_etab[i] = ee0[(l * 6 + f0) * H + cc] + ee1[(l * 3 + f1) * H + cc];
    }
}

// ---------------- GENConv aggregation: warp per dst node ---------------------
// BN fused (hv1 = relu(hv*sc+sh)).  x = hv1 + sum(m*e)/sum(e), written fp16.
__global__ void __launch_bounds__(256) k_agg(const float* __restrict__ beta, int l) {
    __shared__ float etab[18 * H];
    int tid = threadIdx.x;
    for (int i = tid; i < 18 * H; i += 256) etab[i] = g_etab[i];
    __syncthreads();
    int gt   = blockIdx.x * 256 + tid;
    int wid  = gt >> 5;
    int lane = tid & 31;
    if (wid >= NN) return;
    float bl = beta[l];
    int end = g_off[wid];
    int beg = end - g_cnt[wid];
    const float4* __restrict__ hv4 = (const float4*)g_hv;
    const float4* __restrict__ et4 = (const float4*)etab;
    float4 sc = ((const float4*)g_scale)[lane];
    float4 sh = ((const float4*)g_shift)[lane];
    float4 num = make_float4(0.f, 0.f, 0.f, 0.f);
    float4 den = make_float4(0.f, 0.f, 0.f, 0.f);
#define EDGE_ELEM(hc, ec, scc, shc, nc, dc) do {                          \
        float t_ = fmaxf(fmaf(hc, scc, shc), 0.f);                        \
        float m_ = fmaxf(t_ + ec, 0.f) + GEN_EPS;                         \
        float x_ = __expf(m_ * bl);                                       \
        dc += x_; nc = fmaf(m_, x_, nc); } while (0)
#define EDGE_ONE(pe) do {                                                 \
        int src_ = (pe) & 0xFFFF;                                         \
        int idx_ = (pe) >> 16;                                            \
        float4 h_ = hv4[src_ * HV4 + lane];                               \
        float4 e_ = et4[idx_ * HV4 + lane];                               \
        EDGE_ELEM(h_.x, e_.x, sc.x, sh.x, num.x, den.x);                  \
        EDGE_ELEM(h_.y, e_.y, sc.y, sh.y, num.y, den.y);                  \
        EDGE_ELEM(h_.z, e_.z, sc.z, sh.z, num.z, den.z);                  \
        EDGE_ELEM(h_.w, e_.w, sc.w, sh.w, num.w, den.w); } while (0)
    int j = beg;
    for (; j + 2 <= end; j += 2) {
        int pe0 = g_edge[j], pe1 = g_edge[j + 1];
        EDGE_ONE(pe0);
        EDGE_ONE(pe1);
    }
    if (j < end) { int pe0 = g_edge[j]; EDGE_ONE(pe0); }
    float4 hr = hv4[wid * HV4 + lane];
    float4 xo;
    xo.x = fmaxf(fmaf(hr.x, sc.x, sh.x), 0.f);
    xo.y = fmaxf(fmaf(hr.y, sc.y, sh.y), 0.f);
    xo.z = fmaxf(fmaf(hr.z, sc.z, sh.z), 0.f);
    xo.w = fmaxf(fmaf(hr.w, sc.w, sh.w), 0.f);
    if (end > beg) {
        xo.x += num.x / den.x;
        xo.y += num.y / den.y;
        xo.z += num.z / den.z;
        xo.w += num.w / den.w;
    }
    __half2 p0 = __floats2half2_rn(xo.x, xo.y);
    __half2 p1 = __floats2half2_rn(xo.z, xo.w);
    uint2 o;
    o.x = *(unsigned int*)&p0;
    o.y = *(unsigned int*)&p1;
    g_xh[wid * HV4 + lane] = o;
}

// ---------------- MLP GEMM via HMMA: hv = x @ W + b + hv, + BN stats ---------
// 128x128 tile per block, 8 warps, mma.sync m16n8k16 f16->f32, K chunks of 64.
__global__ void __launch_bounds__(256) k_gemm(const __half* __restrict__ Wt,
                                              const float* __restrict__ bias) {
    __shared__ __align__(16) __half As[128 * 72];
    __shared__ __align__(16) __half Bs[128 * 72];
    int tid = threadIdx.x;
    int warp = tid >> 5, lane = tid & 31;
    int row0 = blockIdx.x * 128;
    const __half* xh = (const __half*)g_xh;

    float acc[16][4];
#pragma unroll
    for (int t = 0; t < 16; t++)
#pragma unroll
        for (int j = 0; j < 4; j++) acc[t][j] = 0.f;

#pragma unroll
    for (int kk = 0; kk < H; kk += 64) {
#pragma unroll
        for (int i = 0; i < 4; i++) {
            int f = tid + i * 256;
            int r = f >> 3, c8 = f & 7;
            uint4 v = make_uint4(0, 0, 0, 0);
            if (row0 + r < NN) v = ((const uint4*)(xh + (size_t)(row0 + r) * H + kk))[c8];
            *(uint4*)&As[r * 72 + c8 * 8] = v;
            uint4 w = ((const uint4*)(Wt + r * H + kk))[c8];
            *(uint4*)&Bs[r * 72 + c8 * 8] = w;
        }
        __syncthreads();
        uint32_t a_row = su32(&As[(warp * 16 + (lane & 15)) * 72 + ((lane >> 4) * 8)]);
#pragma unroll
        for (int k = 0; k < 4; k++) {
            uint32_t a0, a1, a2, a3;
            asm volatile("ldmatrix.sync.aligned.m8n8.x4.shared.b16 {%0,%1,%2,%3}, [%4];"
                         : "=r"(a0), "=r"(a1), "=r"(a2), "=r"(a3)
                         : "r"(a_row + k * 32));
#pragma unroll
            for (int p = 0; p < 8; p++) {
                int brow = p * 16 + ((lane >> 4) << 3) + (lane & 7);
                int bcol = k * 16 + ((lane >> 3) & 1) * 8;
                uint32_t baddr = su32(&Bs[brow * 72 + bcol]);
                uint32_t b0, b1, b2, b3;
                asm volatile("ldmatrix.sync.aligned.m8n8.x4.shared.b16 {%0,%1,%2,%3}, [%4];"
                             : "=r"(b0), "=r"(b1), "=r"(b2), "=r"(b3)
                             : "r"(baddr));
                asm volatile("mma.sync.aligned.m16n8k16.row.col.f32.f16.f16.f32 "
                             "{%0,%1,%2,%3}, {%4,%5,%6,%7}, {%8,%9}, {%0,%1,%2,%3};"
                             : "+f"(acc[2 * p][0]), "+f"(acc[2 * p][1]),
                               "+f"(acc[2 * p][2]), "+f"(acc[2 * p][3])
                             : "r"(a0), "r"(a1), "r"(a2), "r"(a3), "r"(b0), "r"(b1));
                asm volatile("mma.sync.aligned.m16n8k16.row.col.f32.f16.f16.f32 "
                             "{%0,%1,%2,%3}, {%4,%5,%6,%7}, {%8,%9}, {%0,%1,%2,%3};"
                             : "+f"(acc[2 * p + 1][0]), "+f"(acc[2 * p + 1][1]),
                               "+f"(acc[2 * p + 1][2]), "+f"(acc[2 * p + 1][3])
                             : "r"(a0), "r"(a1), "r"(a2), "r"(a3), "r"(b2), "r"(b3));
            }
        }
        __syncthreads();
    }
    // epilogue: C + bias + hv_old -> g_hv; fused BN partial stats (deterministic)
    float* sm_s  = (float*)As;        // [8][128]
    float* sm_ss = (float*)Bs;        // [8][128]
    int q = lane & 3, tq = lane >> 2;
    int r0 = row0 + warp * 16 + tq;
    int r1 = r0 + 8;
#pragma unroll
    for (int nt = 0; nt < 16; nt++) {
        int c = nt * 8 + 2 * q;
        float2 bb = *(const float2*)&bias[c];
        float v00 = 0.f, v01 = 0.f, v10 = 0.f, v11 = 0.f;
        if (r0 < NN) {
            float2* h = (float2*)&g_hv[(size_t)r0 * H + c];
            float2 hv = *h;
            v00 = acc[nt][0] + bb.x + hv.x;
            v01 = acc[nt][1] + bb.y + hv.y;
            h->x = v00; h->y = v01;
        }
        if (r1 < NN) {
            float2* h = (float2*)&g_hv[(size_t)r1 * H + c];
            float2 hv = *h;
            v10 = acc[nt][2] + bb.x + hv.x;
            v11 = acc[nt][3] + bb.y + hv.y;
            h->x = v10; h->y = v11;
        }
        float s0 = v00 + v10, s1 = v01 + v11;
        float ss0 = v00 * v00 + v10 * v10, ss1 = v01 * v01 + v11 * v11;
#pragma unroll
        for (int off = 16; off >= 4; off >>= 1) {
            s0  += __shfl_down_sync(0xffffffffu, s0,  off);
            s1  += __shfl_down_sync(0xffffffffu, s1,  off);
            ss0 += __shfl_down_sync(0xffffffffu, ss0, off);
            ss1 += __shfl_down_sync(0xffffffffu, ss1, off);
        }
        if (tq == 0) {
            sm_s [warp * 128 + c]     = s0;
            sm_s [warp * 128 + c + 1] = s1;
            sm_ss[warp * 128 + c]     = ss0;
            sm_ss[warp * 128 + c + 1] = ss1;
        }
    }
    __syncthreads();
    if (tid < 128) {
        float s = 0.f, ss = 0.f;
#pragma unroll
        for (int w = 0; w < 8; w++) { s += sm_s[w * 128 + tid]; ss += sm_ss[w * 128 + tid]; }
        g_part[0][blockIdx.x][tid] = s;
        g_part[1][blockIdx.x][tid] = ss;
    }
}

// ---------------- graph pooling + output head --------------------------------
__global__ void k_pool(const int* __restrict__ gid) {
    int b = blockIdx.x, c = threadIdx.x;
    int n0 = b * BN_CHUNK;
    int n1 = min(NN, n0 + BN_CHUNK);
    if (n0 >= NN) return;
    float acc = 0.f;
    int curg = gid[n0];
    int run = 0;
    for (int n = n0; n < n1; n++) {
        int g = gid[n];
        if (g != curg) {
            atomicAdd(&g_hg[curg * H + c], acc);
            if (c == 0) atomicAdd(&g_cntg[curg], run);
            acc = 0.f; run = 0; curg = g;
        }
        acc += g_hv[n * H + c];
        run++;
    }
    atomicAdd(&g_hg[curg * H + c], acc);
    if (c == 0) atomicAdd(&g_cntg[curg], run);
}

__global__ void k_out(const float* __restrict__ Wo, const float* __restrict__ bo,
                      float* __restrict__ out) {
    int t = threadIdx.x;
    if (t >= GG * OUTD) return;
    int g = t / OUTD, o = t % OUTD;
    float inv = 1.f / (float)g_cntg[g];
    float acc = bo[o];
    for (int h = 0; h < H; h++) acc += g_hg[g * H + h] * inv * Wo[h * OUTD + o];
    out[t] = acc;
}

// ---------------- launch -----------------------------------------------------
extern "C" void kernel_launch(void* const* d_in, const int* in_sizes, int n_in,
                              void* d_out, int out_size) {
    const int* nf0  = (const int*)d_in[0];
    const int* nf1  = (const int*)d_in[1];
    const int* ef0  = (const int*)d_in[2];
    const int* ef1  = (const int*)d_in[3];
    const int* esrc = (const int*)d_in[4];
    const int* edst = (const int*)d_in[5];
    const int* gid  = (const int*)d_in[6];
    int base = (n_in > 7 && in_sizes[7] == 1) ? 8 : 7;
    const float* Wn0  = (const float*)d_in[base + 0];
    const float* Wn1  = (const float*)d_in[base + 1];
    const float* ee0  = (const float*)d_in[base + 2];
    const float* ee1  = (const float*)d_in[base + 3];
    const float* beta = (const float*)d_in[base + 4];
    const float* mlpW = (const float*)d_in[base + 5];
    const float* mlpb = (const float*)d_in[base + 6];
    const float* gam  = (const float*)d_in[base + 7];
    const float* bnb  = (const float*)d_in[base + 8];
    const float* Wo   = (const float*)d_in[base + 9];
    const float* bo   = (const float*)d_in[base + 10];
    float* out = (float*)d_out;

    __half* wh_ptr;
    cudaGetSymbolAddress((void**)&wh_ptr, g_wh);

    k_wt<<<dim3(4, 4, 3), dim3(32, 8)>>>(mlpW);
    k_embed<<<NBC, 128>>>(nf0, nf1, Wn0, Wn1);
    k_count<<<(NE + 255) / 256, 256>>>(edst);
    k_scan1<<<NBC, 128>>>();
    k_scan2<<<1, 512>>>();
    k_scan3<<<NBC, 128>>>();
    k_scatter<<<(NE + 255) / 256, 256>>>(esrc, edst, ef0, ef1);

    for (int l = 0; l < NL; l++) {
        k_bnfin<<<1, 1024>>>(gam, bnb, ee0, ee1, l);
        k_agg<<<(NN * 32 + 255) / 256, 256>>>(beta, l);
        k_gemm<<<NBC, 256>>>(wh_ptr + (size_t)l * H * H, mlpb + (size_t)l * H);
    }

    k_pool<<<BN_BLOCKS, H>>>(gid);
    k_out<<<1, 256>>>(Wo, bo, out);
}